// round 12
// baseline (speedup 1.0000x reference)
#include <cuda_runtime.h>
#include <cuda_bf16.h>

#define BB    4096
#define SS    128
#define DIN   64
#define DOUT  128
#define HH    32
#define NPROD 130          // producer blocks: 128 Wc + 2 bc

// Fused first layer, PACKED: g_Wcp[(d>>2)*HH*4 + j*4 + (d&3)] = (W_net@W1)[d][j]
__device__ float    g_Wcp[DIN * HH];
__device__ float    g_bc[HH];
__device__ unsigned g_flag;   // monotonically increasing across graph replays

// Reduce-scatter butterfly (verified R10): 8 partial sums summed warp-wide;
// lane's result is output o(lane) = 4*b16 + 2*b8 + b4.
__device__ __forceinline__ float reduce8_scatter(
        const float h0, const float h1, const float4 w2v, const int lane) {
    float p0 = h0 * w2v.x, p1 = h0 * w2v.y, p2 = h0 * w2v.z, p3 = h0 * w2v.w;
    float p4 = h1 * w2v.x, p5 = h1 * w2v.y, p6 = h1 * w2v.z, p7 = h1 * w2v.w;
    const bool hi16 = (lane & 16) != 0;
    float q0 = (hi16 ? p4 : p0) + __shfl_xor_sync(0xffffffffu, hi16 ? p0 : p4, 16);
    float q1 = (hi16 ? p5 : p1) + __shfl_xor_sync(0xffffffffu, hi16 ? p1 : p5, 16);
    float q2 = (hi16 ? p6 : p2) + __shfl_xor_sync(0xffffffffu, hi16 ? p2 : p6, 16);
    float q3 = (hi16 ? p7 : p3) + __shfl_xor_sync(0xffffffffu, hi16 ? p3 : p7, 16);
    const bool hi8 = (lane & 8) != 0;
    float r0 = (hi8 ? q2 : q0) + __shfl_xor_sync(0xffffffffu, hi8 ? q0 : q2, 8);
    float r1 = (hi8 ? q3 : q1) + __shfl_xor_sync(0xffffffffu, hi8 ? q1 : q3, 8);
    const bool hi4 = (lane & 4) != 0;
    float s  = (hi4 ? r1 : r0) + __shfl_xor_sync(0xffffffffu, hi4 ? r0 : r1, 4);
    s += __shfl_xor_sync(0xffffffffu, s, 2);
    s += __shfl_xor_sync(0xffffffffu, s, 1);
    return s;
}

// 16-FMA K-slice dot for the weight fold: row = Wnet row (or bnet), k0 = slice.
__device__ __forceinline__ float fold16(const float* __restrict__ row,
                                        const float* __restrict__ W1,
                                        const int k0, const int j) {
    const float4* r4 = reinterpret_cast<const float4*>(row + k0);
    const float4 w0 = r4[0], w1v = r4[1], w2 = r4[2], w3 = r4[3];
    float acc = 0.f;
    acc = fmaf(w0.x,  W1[(k0 +  0) * HH + j], acc);
    acc = fmaf(w0.y,  W1[(k0 +  1) * HH + j], acc);
    acc = fmaf(w0.z,  W1[(k0 +  2) * HH + j], acc);
    acc = fmaf(w0.w,  W1[(k0 +  3) * HH + j], acc);
    acc = fmaf(w1v.x, W1[(k0 +  4) * HH + j], acc);
    acc = fmaf(w1v.y, W1[(k0 +  5) * HH + j], acc);
    acc = fmaf(w1v.z, W1[(k0 +  6) * HH + j], acc);
    acc = fmaf(w1v.w, W1[(k0 +  7) * HH + j], acc);
    acc = fmaf(w2.x,  W1[(k0 +  8) * HH + j], acc);
    acc = fmaf(w2.y,  W1[(k0 +  9) * HH + j], acc);
    acc = fmaf(w2.z,  W1[(k0 + 10) * HH + j], acc);
    acc = fmaf(w2.w,  W1[(k0 + 11) * HH + j], acc);
    acc = fmaf(w3.x,  W1[(k0 + 12) * HH + j], acc);
    acc = fmaf(w3.y,  W1[(k0 + 13) * HH + j], acc);
    acc = fmaf(w3.z,  W1[(k0 + 14) * HH + j], acc);
    acc = fmaf(w3.w,  W1[(k0 + 15) * HH + j], acc);
    return acc;
}

// ---------------------------------------------------------------------------
// Single kernel: blocks 0..NPROD-1 fold the weights (wide/shallow, then
// release via fence+atomic); remaining 1024 blocks are warp-per-batch
// consumers gated by a lane-0 acquire poll (fast-path on graph replays).
// ---------------------------------------------------------------------------
__global__ __launch_bounds__(128, 8) void mono_kernel(
        const float*    __restrict__ x,      // [B, S, DIN]
        const unsigned* __restrict__ mask,   // [B, S] (bits; !=0 test)
        const float*    __restrict__ Wnet,   // [DIN, DOUT]
        const float*    __restrict__ bnet,   // [DOUT]
        const float*    __restrict__ W1,     // [DOUT, HH]
        const float*    __restrict__ b1,     // [HH]
        const float*    __restrict__ W2,     // [HH, 4]
        const float*    __restrict__ b2,     // [4]
        float*          __restrict__ out)    // [B, 2, 4]
{
    const int warp = threadIdx.x >> 5;
    const int lane = threadIdx.x & 31;

    // ============================ PRODUCERS ============================
    if (blockIdx.x < NPROD) {
        const int esub  = lane >> 3;        // warp's 4 elements
        const int slice = lane & 7;         // K-slice (16 k each)
        const int k0    = slice * 16;

        if (blockIdx.x < 128) {
            const int e = ((int)blockIdx.x * 4 + warp) * 4 + esub;  // 0..2047
            const int d = e >> 5, j = e & 31;
            float acc = fold16(Wnet + d * DOUT, W1, k0, j);
            acc += __shfl_xor_sync(0xffffffffu, acc, 4);
            acc += __shfl_xor_sync(0xffffffffu, acc, 2);
            acc += __shfl_xor_sync(0xffffffffu, acc, 1);
            if (slice == 0)
                g_Wcp[(d >> 2) * (HH * 4) + j * 4 + (d & 3)] = acc;
        } else {
            const int j = ((int)blockIdx.x - 128) * 16 + warp * 4 + esub; // 0..31
            float acc = fold16(bnet, W1, k0, j);
            acc += __shfl_xor_sync(0xffffffffu, acc, 4);
            acc += __shfl_xor_sync(0xffffffffu, acc, 2);
            acc += __shfl_xor_sync(0xffffffffu, acc, 1);
            if (slice == 0) g_bc[j] = b1[j] + acc;
        }

        __syncthreads();                    // block writes ordered before...
        if (threadIdx.x == 0) {
            __threadfence();                // ...release fence (130 total)
            atomicAdd(&g_flag, 1u);
        }
        return;
    }

    // ============================ CONSUMERS ============================
    __shared__ __align__(16) float sxx[4][2][DIN];   // per-warp 2-row slab

    const int b     = ((int)blockIdx.x - NPROD) * 4 + warp;
    const float* xb = x + (size_t)b * SS * DIN;

    // ---- prep-independent loads (front-batched) ----
    const uint4 mv = *reinterpret_cast<const uint4*>(mask + (size_t)b * SS + lane * 4);
    const float4 w2v = *reinterpret_cast<const float4*>(W2 + lane * 4);
    const float4 b2v = *reinterpret_cast<const float4*>(b2);

    // ---- mask scan: first two valid positions ----
    unsigned bits = (mv.x != 0u ? 1u : 0u) | (mv.y != 0u ? 2u : 0u)
                  | (mv.z != 0u ? 4u : 0u) | (mv.w != 0u ? 8u : 0u);
    const unsigned any = __ballot_sync(0xffffffffu, bits != 0u);
    const bool valid = (any != 0u);
    int i0 = 0, i1 = 0;
    if (valid) {
        const int t0 = __ffs(any) - 1;
        const unsigned c0 = __shfl_sync(0xffffffffu, bits, t0);
        i0 = t0 * 4 + (__ffs(c0) - 1);
        const unsigned c0r = c0 & (c0 - 1);
        if (c0r) {
            i1 = t0 * 4 + (__ffs(c0r) - 1);
        } else {
            const unsigned any2 = any & (any - 1);
            if (any2) {
                const int t1 = __ffs(any2) - 1;
                const unsigned c1 = __shfl_sync(0xffffffffu, bits, t1);
                i1 = t1 * 4 + (__ffs(c1) - 1);
            } else {
                i1 = i0;          // nv==1: top2 = preds[:,0]
            }
        }
    }

    // ---- exact gather: half-warp per row, one LDG.128 per lane ----
    {
        const int r   = lane >> 4;                    // 0/1
        const int c   = (lane & 15) * 4;
        const int row = r ? i1 : i0;
        *reinterpret_cast<float4*>(&sxx[warp][r][c]) =
            *reinterpret_cast<const float4*>(xb + (size_t)row * DIN + c);
    }

    // ---- acquire the folded weights: lane-0 poll, fast-path on replays ----
    if (lane == 0) {
        unsigned f;
        asm volatile("ld.acquire.gpu.global.b32 %0, [%1];"
                     : "=r"(f) : "l"(&g_flag) : "memory");
        while (f < (unsigned)NPROD) {
            __nanosleep(200);
            asm volatile("ld.acquire.gpu.global.b32 %0, [%1];"
                         : "=r"(f) : "l"(&g_flag) : "memory");
        }
    }
    __syncwarp();    // all lanes held until lane 0's acquire succeeds

    const float  bcj = g_bc[lane];
    const float* xr0 = sxx[warp][0];
    const float* xr1 = sxx[warp][1];
    const float* wp  = g_Wcp + lane * 4;     // this lane's j-column, packed

    float a0 = 0.f, a1 = 0.f, a2 = 0.f, a3 = 0.f;
    float c0 = 0.f, c1 = 0.f, c2 = 0.f, c3 = 0.f;
    #pragma unroll 4
    for (int d4 = 0; d4 < DIN / 4; d4++) {
        const float4 wv = *reinterpret_cast<const float4*>(wp + d4 * (HH * 4));
        const float4 x0 = *reinterpret_cast<const float4*>(xr0 + d4 * 4);
        const float4 x1 = *reinterpret_cast<const float4*>(xr1 + d4 * 4);
        a0 = fmaf(x0.x, wv.x, a0); c0 = fmaf(x1.x, wv.x, c0);
        a1 = fmaf(x0.y, wv.y, a1); c1 = fmaf(x1.y, wv.y, c1);
        a2 = fmaf(x0.z, wv.z, a2); c2 = fmaf(x1.z, wv.z, c2);
        a3 = fmaf(x0.w, wv.w, a3); c3 = fmaf(x1.w, wv.w, c3);
    }
    const float h0 = fmaxf(bcj + (a0 + a1) + (a2 + a3), 0.f);
    const float h1 = fmaxf(bcj + (c0 + c1) + (c2 + c3), 0.f);

    // ---- layer 2: reduce-scatter, 8 lanes store one scalar each ----
    const float s = reduce8_scatter(h0, h1, w2v, lane);

    if ((lane & 3) == 0) {
        const int o = ((lane >> 4) & 1) * 4 + ((lane >> 3) & 1) * 2 + ((lane >> 2) & 1);
        const float bias = (o & 2) ? ((o & 1) ? b2v.w : b2v.z)
                                   : ((o & 1) ? b2v.y : b2v.x);
        out[(size_t)b * 8 + o] = valid ? (s + bias) : 0.f;
    }
}

// ---------------------------------------------------------------------------
// Inputs (metadata order): x, W_net, b_net, W1, b1, W2, b2, mask
// Output: float32 [4096, 2, 4]
// ---------------------------------------------------------------------------
extern "C" void kernel_launch(void* const* d_in, const int* in_sizes, int n_in,
                              void* d_out, int out_size) {
    const float*    x    = (const float*)d_in[0];
    const float*    Wnet = (const float*)d_in[1];
    const float*    bnet = (const float*)d_in[2];
    const float*    W1   = (const float*)d_in[3];
    const float*    b1   = (const float*)d_in[4];
    const float*    W2   = (const float*)d_in[5];
    const float*    b2   = (const float*)d_in[6];
    const unsigned* mask = (const unsigned*)d_in[7];
    float* out = (float*)d_out;

    mono_kernel<<<NPROD + BB / 4, 128>>>(x, mask, Wnet, bnet, W1, b1,
                                         W2, b2, out);
}

// round 16
// speedup vs baseline: 1.4706x; 1.4706x over previous
#include <cuda_runtime.h>
#include <cuda_bf16.h>

#define BB   4096
#define SS   128
#define DIN  64
#define DOUT 128
#define HH   32

// Fused first layer, PACKED: g_Wcp[(d>>2)*HH*4 + j*4 + (d&3)] = (W_net@W1)[d][j]
__device__ float g_Wcp[DIN * HH];
__device__ float g_bc[HH];

// ---------------------------------------------------------------------------
// Prologue: warp-per-element fold (32-way K split + butterfly), 260 x 8 warps.
// Wide and shallow (its DURATION sits on every consumer's critical path).
// ---------------------------------------------------------------------------
__global__ __launch_bounds__(256) void prep_kernel(
        const float* __restrict__ Wnet, const float* __restrict__ bnet,
        const float* __restrict__ W1,   const float* __restrict__ b1) {
    cudaTriggerProgrammaticLaunchCompletion();

    const int warp = threadIdx.x >> 5;
    const int lane = threadIdx.x & 31;
    const int we   = blockIdx.x * 8 + warp;

    if (we < DIN * HH) {
        const int d = we >> 5, j = we & 31;
        const float4 wn = *reinterpret_cast<const float4*>(Wnet + d * DOUT + lane * 4);
        const int k = lane * 4;
        float acc = wn.x * W1[(k + 0) * HH + j];
        acc = fmaf(wn.y, W1[(k + 1) * HH + j], acc);
        acc = fmaf(wn.z, W1[(k + 2) * HH + j], acc);
        acc = fmaf(wn.w, W1[(k + 3) * HH + j], acc);
        #pragma unroll
        for (int off = 16; off; off >>= 1)
            acc += __shfl_xor_sync(0xffffffffu, acc, off);
        if (lane == 0)
            g_Wcp[(d >> 2) * (HH * 4) + j * 4 + (d & 3)] = acc;
    } else if (we < DIN * HH + HH) {
        const int j = we - DIN * HH;
        const int k = lane * 4;
        float acc = bnet[k + 0] * W1[(k + 0) * HH + j];
        acc = fmaf(bnet[k + 1], W1[(k + 1) * HH + j], acc);
        acc = fmaf(bnet[k + 2], W1[(k + 2) * HH + j], acc);
        acc = fmaf(bnet[k + 3], W1[(k + 3) * HH + j], acc);
        #pragma unroll
        for (int off = 16; off; off >>= 1)
            acc += __shfl_xor_sync(0xffffffffu, acc, off);
        if (lane == 0) g_bc[j] = b1[j] + acc;
    }
}

// Full 128-entry mask scan (fallback path, warp-uniform): first two valid.
__device__ __forceinline__ void scan_mask_full(
        const unsigned* __restrict__ mrow, const int lane,
        bool& valid, int& i0, int& i1) {
    const uint4 mv = *reinterpret_cast<const uint4*>(mrow + lane * 4);
    unsigned bits = (mv.x != 0u ? 1u : 0u) | (mv.y != 0u ? 2u : 0u)
                  | (mv.z != 0u ? 4u : 0u) | (mv.w != 0u ? 8u : 0u);
    const unsigned any = __ballot_sync(0xffffffffu, bits != 0u);
    valid = (any != 0u);
    i0 = 0; i1 = 0;
    if (valid) {
        const int t0 = __ffs(any) - 1;
        const unsigned c0 = __shfl_sync(0xffffffffu, bits, t0);
        i0 = t0 * 4 + (__ffs(c0) - 1);
        const unsigned c0r = c0 & (c0 - 1);
        if (c0r) {
            i1 = t0 * 4 + (__ffs(c0r) - 1);
        } else {
            const unsigned any2 = any & (any - 1);
            if (any2) {
                const int t1 = __ffs(any2) - 1;
                const unsigned c1 = __shfl_sync(0xffffffffu, bits, t1);
                i1 = t1 * 4 + (__ffs(c1) - 1);
            } else {
                i1 = i0;          // nv==1: top2 = preds[:,0]
            }
        }
    }
}

// Reduce-scatter butterfly (verified R10): 8 partial sums summed warp-wide;
// lane's result is output o(lane) = 4*b16 + 2*b8 + b4.
__device__ __forceinline__ float reduce8_scatter(
        const float h0, const float h1, const float4 w2v, const int lane) {
    float p0 = h0 * w2v.x, p1 = h0 * w2v.y, p2 = h0 * w2v.z, p3 = h0 * w2v.w;
    float p4 = h1 * w2v.x, p5 = h1 * w2v.y, p6 = h1 * w2v.z, p7 = h1 * w2v.w;
    const bool hi16 = (lane & 16) != 0;
    float q0 = (hi16 ? p4 : p0) + __shfl_xor_sync(0xffffffffu, hi16 ? p0 : p4, 16);
    float q1 = (hi16 ? p5 : p1) + __shfl_xor_sync(0xffffffffu, hi16 ? p1 : p5, 16);
    float q2 = (hi16 ? p6 : p2) + __shfl_xor_sync(0xffffffffu, hi16 ? p2 : p6, 16);
    float q3 = (hi16 ? p7 : p3) + __shfl_xor_sync(0xffffffffu, hi16 ? p3 : p7, 16);
    const bool hi8 = (lane & 8) != 0;
    float r0 = (hi8 ? q2 : q0) + __shfl_xor_sync(0xffffffffu, hi8 ? q0 : q2, 8);
    float r1 = (hi8 ? q3 : q1) + __shfl_xor_sync(0xffffffffu, hi8 ? q1 : q3, 8);
    const bool hi4 = (lane & 4) != 0;
    float s  = (hi4 ? r1 : r0) + __shfl_xor_sync(0xffffffffu, hi4 ? r0 : r1, 4);
    s += __shfl_xor_sync(0xffffffffu, s, 2);
    s += __shfl_xor_sync(0xffffffffu, s, 1);
    return s;
}

// ---------------------------------------------------------------------------
// Main kernel: TWO batches per warp; FAST 8-entry mask scan (1 sector/batch,
// covers 99.87% of batches; nv>=2 guaranteed on the fast path) with full-row
// fallback. 1024 blocks x 64 threads.
// ---------------------------------------------------------------------------
__global__ __launch_bounds__(64, 8) void fused_kernel(
        const float*    __restrict__ x,      // [B, S, DIN]
        const unsigned* __restrict__ mask,   // [B, S] (bits; !=0 test)
        const float*    __restrict__ W2,     // [HH, 4]
        const float*    __restrict__ b2,     // [4]
        float*          __restrict__ out)    // [B, 2, 4]
{
    __shared__ __align__(16) float sxx[2][4][DIN];   // per-warp 4-row slab

    const int warp = threadIdx.x >> 5;
    const int lane = threadIdx.x & 31;
    const int b0   = blockIdx.x * 4 + warp * 2;
    const int b1   = b0 + 1;

    // ---- fast mask probe: lanes 0-7 -> A[0..7], lanes 8-15 -> B[0..7] ----
    const int probe_b = (lane & 8) ? b1 : b0;     // lanes >=16 duplicate A (ignored)
    const unsigned mval = mask[(size_t)probe_b * SS + (lane & 7)];
    const float4 w2v = *reinterpret_cast<const float4*>(W2 + lane * 4);
    const float4 b2v = *reinterpret_cast<const float4*>(b2);

    const unsigned bal = __ballot_sync(0xffffffffu, mval != 0u);
    const unsigned bfA = bal & 0xFFu;
    const unsigned bfB = (bal >> 8) & 0xFFu;

    bool validA = true, validB = true;
    int i0A, i1A, i0B, i1B;

    if (__popc(bfA) >= 2) {            // warp-uniform
        i0A = __ffs(bfA) - 1;
        i1A = __ffs(bfA & (bfA - 1)) - 1;
    } else {
        scan_mask_full(mask + (size_t)b0 * SS, lane, validA, i0A, i1A);
    }
    if (__popc(bfB) >= 2) {            // warp-uniform
        i0B = __ffs(bfB) - 1;
        i1B = __ffs(bfB & (bfB - 1)) - 1;
    } else {
        scan_mask_full(mask + (size_t)b1 * SS, lane, validB, i0B, i1B);
    }

    // ---- gather 4 rows: quarter-warp per row, 2 LDG.128 per lane ----
    {
        const int r  = lane >> 3;                    // 0..3
        const int c  = (lane & 7) * 8;               // 0,8,..,56
        const int bb = (r < 2) ? b0 : b1;
        const int row = (r == 0) ? i0A : (r == 1) ? i1A : (r == 2) ? i0B : i1B;
        const float* src = x + ((size_t)bb * SS + row) * DIN + c;
        *reinterpret_cast<float4*>(&sxx[warp][r][c])     =
            *reinterpret_cast<const float4*>(src);
        *reinterpret_cast<float4*>(&sxx[warp][r][c + 4]) =
            *reinterpret_cast<const float4*>(src + 4);
    }
    __syncwarp();

    // ---- wait for folded weights, then compute ----
    cudaGridDependencySynchronize();

    const float  bcj = g_bc[lane];
    const float* wp  = g_Wcp + lane * 4;

    // h-layer: 16 weight loads shared by 4 rows; 2 accums per row
    float aA0 = 0.f, bA0 = 0.f, aA1 = 0.f, bA1 = 0.f;
    float aB0 = 0.f, bB0 = 0.f, aB1 = 0.f, bB1 = 0.f;
    #pragma unroll 8
    for (int d4 = 0; d4 < DIN / 4; d4++) {
        const float4 wv = *reinterpret_cast<const float4*>(wp + d4 * (HH * 4));
        const float4 xA0 = *reinterpret_cast<const float4*>(&sxx[warp][0][d4 * 4]);
        const float4 xA1 = *reinterpret_cast<const float4*>(&sxx[warp][1][d4 * 4]);
        const float4 xB0 = *reinterpret_cast<const float4*>(&sxx[warp][2][d4 * 4]);
        const float4 xB1 = *reinterpret_cast<const float4*>(&sxx[warp][3][d4 * 4]);
        aA0 = fmaf(xA0.x, wv.x, aA0); bA0 = fmaf(xA0.y, wv.y, bA0);
        aA0 = fmaf(xA0.z, wv.z, aA0); bA0 = fmaf(xA0.w, wv.w, bA0);
        aA1 = fmaf(xA1.x, wv.x, aA1); bA1 = fmaf(xA1.y, wv.y, bA1);
        aA1 = fmaf(xA1.z, wv.z, aA1); bA1 = fmaf(xA1.w, wv.w, bA1);
        aB0 = fmaf(xB0.x, wv.x, aB0); bB0 = fmaf(xB0.y, wv.y, bB0);
        aB0 = fmaf(xB0.z, wv.z, aB0); bB0 = fmaf(xB0.w, wv.w, bB0);
        aB1 = fmaf(xB1.x, wv.x, aB1); bB1 = fmaf(xB1.y, wv.y, bB1);
        aB1 = fmaf(xB1.z, wv.z, aB1); bB1 = fmaf(xB1.w, wv.w, bB1);
    }
    const float hA0 = fmaxf(bcj + aA0 + bA0, 0.f);
    const float hA1 = fmaxf(bcj + aA1 + bA1, 0.f);
    const float hB0 = fmaxf(bcj + aB0 + bB0, 0.f);
    const float hB1 = fmaxf(bcj + aB1 + bB1, 0.f);

    // ---- layer 2: reduce-scatter per batch ----
    const float sA = reduce8_scatter(hA0, hA1, w2v, lane);
    const float sB = reduce8_scatter(hB0, hB1, w2v, lane);

    if ((lane & 3) == 0) {
        const int o = ((lane >> 4) & 1) * 4 + ((lane >> 3) & 1) * 2 + ((lane >> 2) & 1);
        const float bias = (o & 2) ? ((o & 1) ? b2v.w : b2v.z)
                                   : ((o & 1) ? b2v.y : b2v.x);
        out[(size_t)b0 * 8 + o] = validA ? (sA + bias) : 0.f;
        out[(size_t)b1 * 8 + o] = validB ? (sB + bias) : 0.f;
    }
}

// ---------------------------------------------------------------------------
// Inputs (metadata order): x, W_net, b_net, W1, b1, W2, b2, mask
// Output: float32 [4096, 2, 4]
// ---------------------------------------------------------------------------
extern "C" void kernel_launch(void* const* d_in, const int* in_sizes, int n_in,
                              void* d_out, int out_size) {
    const float*    x    = (const float*)d_in[0];
    const float*    Wnet = (const float*)d_in[1];
    const float*    bnet = (const float*)d_in[2];
    const float*    W1   = (const float*)d_in[3];
    const float*    b1   = (const float*)d_in[4];
    const float*    W2   = (const float*)d_in[5];
    const float*    b2   = (const float*)d_in[6];
    const unsigned* mask = (const unsigned*)d_in[7];
    float* out = (float*)d_out;

    // Producer (wide, shallow)
    prep_kernel<<<260, 256>>>(Wnet, bnet, W1, b1);

    // Consumer with programmatic dependent launch.
    cudaLaunchConfig_t cfg = {};
    cfg.gridDim  = dim3(BB / 4, 1, 1);     // 1024 blocks
    cfg.blockDim = dim3(64, 1, 1);         // 2 warps x 2 batches
    cfg.dynamicSmemBytes = 0;
    cfg.stream = 0;
    cudaLaunchAttribute attr[1];
    attr[0].id = cudaLaunchAttributeProgrammaticStreamSerialization;
    attr[0].val.programmaticStreamSerializationAllowed = 1;
    cfg.attrs = attr;
    cfg.numAttrs = 1;
    cudaLaunchKernelEx(&cfg, fused_kernel, x, mask, W2, b2, out);
}